// round 7
// baseline (speedup 1.0000x reference)
#include <cuda_runtime.h>
#include <math.h>

#define DIMX   20
#define DD     21
#define NPT    2048
#define MCc    32
#define UNITS  128
#define TP     16
#define BTOT   69632
#define NTILES (BTOT / TP)

#define SIGc   0.2f
#define MUc    0.05f
#define Rc     0.05f
#define DELTAc 0.01f

__device__ float g_L[DIMX * DIMX];
__device__ float g_WT[4 * UNITS * UNITS];
__device__ float g_UcatT[5 * UNITS * 24];
__device__ float g_X[BTOT * DD];
__device__ float g_FP[BTOT * DD];
__device__ float g_FVAL[BTOT];

#define SM_X    0
#define SM_XU   336
#define SM_S    (SM_XU + 4 * 2048)
#define SM_Z    (SM_S + 3 * 2048)
#define SM_G    (SM_Z + 3 * 2048)
#define SM_R    (SM_G + 3 * 2048)
#define SM_H    (SM_R + 3 * 2048)
#define SM_FRED (SM_H + 3 * 2048)
#define SM_TOT  (SM_FRED + 64)

__global__ void prep_kernel(const float* __restrict__ wz, const float* __restrict__ wg,
                            const float* __restrict__ wr, const float* __restrict__ wh,
                            const float* __restrict__ uz, const float* __restrict__ ug,
                            const float* __restrict__ ur, const float* __restrict__ uh,
                            const float* __restrict__ w1)
{
    int idx = blockIdx.x * blockDim.x + threadIdx.x;
    int stride = gridDim.x * blockDim.x;

    for (int t = idx; t < 4 * UNITS * UNITS; t += stride) {
        int mat = t >> 14;
        int r   = t & 16383;
        int j   = r >> 7;
        int k   = r & 127;
        const float* W = (mat == 0) ? wz : (mat == 1) ? wg : (mat == 2) ? wr : wh;
        g_WT[t] = W[k * UNITS + j];
    }
    for (int t = idx; t < 5 * UNITS * DD; t += stride) {
        int v = t / (UNITS * DD);
        int r = t % (UNITS * DD);
        int j = r / DD;
        int d = r % DD;
        const float* U = (v == 0) ? uz : (v == 1) ? ug : (v == 2) ? ur : (v == 3) ? uh : w1;
        g_UcatT[(v * UNITS + j) * 24 + d] = U[d * UNITS + j];
    }
    if (idx == 0) {
        // cov = DELTA*(RHO*ones + (1-RHO)*I); cholesky in double (matches numpy), cast to f32
        double Ld[DIMX][DIMX];
        for (int i = 0; i < DIMX; i++) {
            for (int j2 = 0; j2 <= i; j2++) {
                double s = 0.01 * (0.5 + (i == j2 ? 0.5 : 0.0));
                for (int k = 0; k < j2; k++) s -= Ld[i][k] * Ld[j2][k];
                Ld[i][j2] = (i == j2) ? sqrt(s) : s / Ld[j2][j2];
            }
        }
        for (int i = 0; i < DIMX; i++)
            for (int j2 = 0; j2 < DIMX; j2++)
                g_L[i * DIMX + j2] = (j2 <= i) ? (float)Ld[i][j2] : 0.0f;
    }
}

__global__ void build_kernel(const float* __restrict__ inputs, const float* __restrict__ eps)
{
    int r = blockIdx.x * blockDim.x + threadIdx.x;
    if (r >= BTOT) return;
    if (r < 4096) {
        #pragma unroll
        for (int d = 0; d < DD; d++) g_X[r * DD + d] = inputs[r * DD + d];
    } else {
        int q = r - 4096;
        int m = q >> 11;
        int n = q & 2047;
        float xr[DD];
        #pragma unroll
        for (int d = 0; d < DD; d++) xr[d] = inputs[n * DD + d];
        float e[DIMX];
        #pragma unroll
        for (int d = 0; d < DIMX; d++) e[d] = eps[(m * NPT + n) * DIMX + d];
        #pragma unroll
        for (int k = 0; k < DIMX; k++) {
            float acc = 0.f;
            #pragma unroll
            for (int d = 0; d < DIMX; d++) acc += e[d] * g_L[k * DIMX + d];
            float sample = xr[k] + acc;
            float viol = sample * (SIGc * xr[k]);
            g_X[r * DD + k] = xr[k] + viol;
        }
        g_X[r * DD + DIMX] = xr[DIMX];
    }
}

__device__ __forceinline__ void ld8(float a[8], const float* src, int j, int p0) {
    float4 x = *(const float4*)&src[j * TP + p0];
    float4 y = *(const float4*)&src[j * TP + p0 + 4];
    a[0]=x.x; a[1]=x.y; a[2]=x.z; a[3]=x.w; a[4]=y.x; a[5]=y.y; a[6]=y.z; a[7]=y.w;
}
__device__ __forceinline__ void st8(float* dst, const float a[8], int j, int p0) {
    *(float4*)&dst[j * TP + p0]     = make_float4(a[0], a[1], a[2], a[3]);
    *(float4*)&dst[j * TP + p0 + 4] = make_float4(a[4], a[5], a[6], a[7]);
}
__device__ __forceinline__ void mm_acc(float acc[8], const float* __restrict__ W,
                                       const float* S, int j, int p0) {
    #pragma unroll 4
    for (int k = 0; k < UNITS; k++) {
        float wv = W[k * UNITS + j];
        float4 a = *(const float4*)&S[k * TP + p0];
        float4 b = *(const float4*)&S[k * TP + p0 + 4];
        acc[0] += a.x*wv; acc[1] += a.y*wv; acc[2] += a.z*wv; acc[3] += a.w*wv;
        acc[4] += b.x*wv; acc[5] += b.y*wv; acc[6] += b.z*wv; acc[7] += b.w*wv;
    }
}
__device__ __forceinline__ void mm_acc_sr(float acc[8], const float* __restrict__ W,
                                          const float* S, const float* Rr, int j, int p0) {
    #pragma unroll 4
    for (int k = 0; k < UNITS; k++) {
        float wv = W[k * UNITS + j];
        float4 a  = *(const float4*)&S[k * TP + p0];
        float4 b  = *(const float4*)&S[k * TP + p0 + 4];
        float4 r1 = *(const float4*)&Rr[k * TP + p0];
        float4 r2 = *(const float4*)&Rr[k * TP + p0 + 4];
        acc[0] += a.x*r1.x*wv; acc[1] += a.y*r1.y*wv; acc[2] += a.z*r1.z*wv; acc[3] += a.w*r1.w*wv;
        acc[4] += b.x*r2.x*wv; acc[5] += b.y*r2.y*wv; acc[6] += b.z*r2.z*wv; acc[7] += b.w*r2.w*wv;
    }
}
__device__ __forceinline__ void mm_x(float acc[8], const float* __restrict__ U,
                                     const float* X, int j, int p0) {
    #pragma unroll
    for (int d = 0; d < DD; d++) {
        float wv = U[d * UNITS + j];
        float4 a = *(const float4*)&X[d * TP + p0];
        float4 b = *(const float4*)&X[d * TP + p0 + 4];
        acc[0] += a.x*wv; acc[1] += a.y*wv; acc[2] += a.z*wv; acc[3] += a.w*wv;
        acc[4] += b.x*wv; acc[5] += b.y*wv; acc[6] += b.z*wv; acc[7] += b.w*wv;
    }
}

__global__ __launch_bounds__(256, 1)
void dgm_main(const float* __restrict__ w1, const float* __restrict__ b1,
              const float* __restrict__ uz, const float* __restrict__ wz, const float* __restrict__ bz,
              const float* __restrict__ ug, const float* __restrict__ wg, const float* __restrict__ bg,
              const float* __restrict__ ur, const float* __restrict__ wr, const float* __restrict__ br,
              const float* __restrict__ uh, const float* __restrict__ wh, const float* __restrict__ bh,
              const float* __restrict__ wout, const float* __restrict__ bout)
{
    extern __shared__ float sm[];
    const int tid = threadIdx.x;
    const int j   = tid & 127;
    const int pg  = tid >> 7;
    const int p0  = pg * 8;
    const int base = blockIdx.x * TP;
    const bool doGrad = !(blockIdx.x >= 128 && blockIdx.x < 256);

    for (int t = tid; t < TP * DD; t += 256) {
        int p = t / DD, d = t % DD;
        sm[SM_X + d * TP + p] = g_X[(base + p) * DD + d];
    }
    __syncthreads();

    // x@U + b (shared across layers) and s0
    {
        float acc[8];
        float bb = bz[j];
        #pragma unroll
        for (int p = 0; p < 8; p++) acc[p] = bb;
        mm_x(acc, uz, &sm[SM_X], j, p0); st8(&sm[SM_XU + 0 * 2048], acc, j, p0);

        bb = bg[j];
        #pragma unroll
        for (int p = 0; p < 8; p++) acc[p] = bb;
        mm_x(acc, ug, &sm[SM_X], j, p0); st8(&sm[SM_XU + 1 * 2048], acc, j, p0);

        bb = br[j];
        #pragma unroll
        for (int p = 0; p < 8; p++) acc[p] = bb;
        mm_x(acc, ur, &sm[SM_X], j, p0); st8(&sm[SM_XU + 2 * 2048], acc, j, p0);

        bb = bh[j];
        #pragma unroll
        for (int p = 0; p < 8; p++) acc[p] = bb;
        mm_x(acc, uh, &sm[SM_X], j, p0); st8(&sm[SM_XU + 3 * 2048], acc, j, p0);

        bb = b1[j];
        #pragma unroll
        for (int p = 0; p < 8; p++) acc[p] = bb;
        mm_x(acc, w1, &sm[SM_X], j, p0);
        #pragma unroll
        for (int p = 0; p < 8; p++) acc[p] = tanhf(acc[p]);
        st8(&sm[SM_S + 0 * 2048], acc, j, p0);
    }
    __syncthreads();

    // ---- forward ----
    float s3v[8];
    #pragma unroll 1
    for (int l = 0; l < 3; l++) {
        float* Sin = &sm[SM_S + l * 2048];
        float* ZA  = &sm[SM_Z + l * 2048];
        float* GA  = &sm[SM_G + l * 2048];
        float* RA  = &sm[SM_R + l * 2048];
        float* HA  = &sm[SM_H + l * 2048];

        float z8[8], g8[8], h8[8];
        {
            float acc[8]; ld8(acc, &sm[SM_XU + 0 * 2048], j, p0);
            mm_acc(acc, wz, Sin, j, p0);
            #pragma unroll
            for (int p = 0; p < 8; p++) z8[p] = tanhf(acc[p]);
            st8(ZA, z8, j, p0);
        }
        {
            float acc[8]; ld8(acc, &sm[SM_XU + 1 * 2048], j, p0);
            mm_acc(acc, wg, Sin, j, p0);
            #pragma unroll
            for (int p = 0; p < 8; p++) g8[p] = tanhf(acc[p]);
            st8(GA, g8, j, p0);
        }
        {
            float acc[8]; ld8(acc, &sm[SM_XU + 2 * 2048], j, p0);
            mm_acc(acc, wr, Sin, j, p0);
            float r8[8];
            #pragma unroll
            for (int p = 0; p < 8; p++) r8[p] = tanhf(acc[p]);
            st8(RA, r8, j, p0);
        }
        __syncthreads();
        {
            float acc[8]; ld8(acc, &sm[SM_XU + 3 * 2048], j, p0);
            mm_acc_sr(acc, wh, Sin, RA, j, p0);
            #pragma unroll
            for (int p = 0; p < 8; p++) h8[p] = tanhf(acc[p]);
            st8(HA, h8, j, p0);
        }
        float sl8[8]; ld8(sl8, Sin, j, p0);
        if (l < 2) {
            float sn[8];
            #pragma unroll
            for (int p = 0; p < 8; p++) sn[p] = (1.0f - g8[p]) * h8[p] + z8[p] * sl8[p];
            st8(&sm[SM_S + (l + 1) * 2048], sn, j, p0);
            __syncthreads();
        } else {
            #pragma unroll
            for (int p = 0; p < 8; p++) s3v[p] = (1.0f - g8[p]) * h8[p] + z8[p] * sl8[p];
        }
    }

    // ---- value: f = s3@w + b ----
    {
        float wv = wout[j];
        int warpId = tid >> 5;
        #pragma unroll
        for (int p = 0; p < 8; p++) {
            float v = wv * s3v[p];
            #pragma unroll
            for (int off = 16; off; off >>= 1) v += __shfl_xor_sync(0xffffffffu, v, off);
            if ((tid & 31) == 0) sm[SM_FRED + warpId * 8 + p] = v;
        }
        __syncthreads();
        if (tid < TP) {
            int p = tid;
            int pgp = p >> 3;
            float f = bout[0];
            #pragma unroll
            for (int w4 = 0; w4 < 4; w4++) f += sm[SM_FRED + (pgp * 4 + w4) * 8 + (p & 7)];
            g_FVAL[base + p] = f;
        }
    }

    if (!doGrad) return;

    // ---- backward: grad wrt x ----
    float ds[8];
    {
        float wv = wout[j];
        float zz[8];
        #pragma unroll
        for (int p = 0; p < 8; p++) { ds[p] = wv; zz[p] = 0.f; }
        st8(&sm[SM_XU + 0 * 2048], zz, j, p0);
        st8(&sm[SM_XU + 1 * 2048], zz, j, p0);
        st8(&sm[SM_XU + 2 * 2048], zz, j, p0);
        st8(&sm[SM_XU + 3 * 2048], zz, j, p0);
    }

    #pragma unroll 1
    for (int l = 2; l >= 0; l--) {
        float* Sin = &sm[SM_S + l * 2048];
        float* ZA  = &sm[SM_Z + l * 2048];
        float* GA  = &sm[SM_G + l * 2048];
        float* RA  = &sm[SM_R + l * 2048];
        float* HA  = &sm[SM_H + l * 2048];

        // stage A: elementwise grads; overwrite Z/G/H with daz/dag/dah; accumulate sums
        #pragma unroll
        for (int p = 0; p < 8; p++) {
            int o = j * TP + p0 + p;
            float z = ZA[o], g = GA[o], h = HA[o], sl = Sin[o];
            float dsp = ds[p];
            float dh = dsp * (1.0f - g);
            float dg = -dsp * h;
            float dz = dsp * sl;
            float daz = dz * (1.0f - z * z);
            float dag = dg * (1.0f - g * g);
            float dah = dh * (1.0f - h * h);
            ZA[o] = daz; GA[o] = dag; HA[o] = dah;
            sm[SM_XU + 0 * 2048 + o] += daz;
            sm[SM_XU + 1 * 2048 + o] += dag;
            sm[SM_XU + 3 * 2048 + o] += dah;
            ds[p] = dsp * z;
        }
        __syncthreads();

        // stage B: dsr = dah @ Wh^T
        float dsr[8];
        #pragma unroll
        for (int p = 0; p < 8; p++) dsr[p] = 0.f;
        {
            const float* WhT = g_WT + 3 * UNITS * UNITS;
            #pragma unroll 4
            for (int k = 0; k < UNITS; k++) {
                float wt = WhT[k * UNITS + j];
                float4 a = *(const float4*)&HA[k * TP + p0];
                float4 b = *(const float4*)&HA[k * TP + p0 + 4];
                dsr[0] += a.x*wt; dsr[1] += a.y*wt; dsr[2] += a.z*wt; dsr[3] += a.w*wt;
                dsr[4] += b.x*wt; dsr[5] += b.y*wt; dsr[6] += b.z*wt; dsr[7] += b.w*wt;
            }
        }
        // stage C: dar; overwrite R slot; accumulate
        #pragma unroll
        for (int p = 0; p < 8; p++) {
            int o = j * TP + p0 + p;
            float r = RA[o], sl = Sin[o];
            ds[p] += dsr[p] * r;
            float dar = (dsr[p] * sl) * (1.0f - r * r);
            RA[o] = dar;
            sm[SM_XU + 2 * 2048 + o] += dar;
        }
        __syncthreads();

        // stage D: ds += daz@Wz^T + dag@Wg^T + dar@Wr^T
        {
            const float* WzT = g_WT + 0 * UNITS * UNITS;
            const float* WgT = g_WT + 1 * UNITS * UNITS;
            const float* WrT = g_WT + 2 * UNITS * UNITS;
            #pragma unroll 2
            for (int k = 0; k < UNITS; k++) {
                float az = WzT[k * UNITS + j];
                float ag = WgT[k * UNITS + j];
                float ar = WrT[k * UNITS + j];
                float4 z1 = *(const float4*)&ZA[k * TP + p0];
                float4 z2 = *(const float4*)&ZA[k * TP + p0 + 4];
                float4 g1 = *(const float4*)&GA[k * TP + p0];
                float4 g2 = *(const float4*)&GA[k * TP + p0 + 4];
                float4 r1 = *(const float4*)&RA[k * TP + p0];
                float4 r2 = *(const float4*)&RA[k * TP + p0 + 4];
                ds[0] += z1.x*az + g1.x*ag + r1.x*ar;
                ds[1] += z1.y*az + g1.y*ag + r1.y*ar;
                ds[2] += z1.z*az + g1.z*ag + r1.z*ar;
                ds[3] += z1.w*az + g1.w*ag + r1.w*ar;
                ds[4] += z2.x*az + g2.x*ag + r2.x*ar;
                ds[5] += z2.y*az + g2.y*ag + r2.y*ar;
                ds[6] += z2.z*az + g2.z*ag + r2.z*ar;
                ds[7] += z2.w*az + g2.w*ag + r2.w*ar;
            }
        }
        // next stage A touches only layer l-1 arrays at own elements: no barrier needed
    }

    // da1 = ds * (1 - s0^2), overwrite S0
    #pragma unroll
    for (int p = 0; p < 8; p++) {
        int o = j * TP + p0 + p;
        float s0 = sm[SM_S + o];
        sm[SM_S + o] = ds[p] * (1.0f - s0 * s0);
    }
    __syncthreads();

    // dx = sum_v Da_v @ U_v^T  (coalesced write)
    for (int o = tid; o < DD * TP; o += 256) {
        int d = o % DD;
        int p = o / DD;
        float acc = 0.f;
        #pragma unroll 1
        for (int v = 0; v < 5; v++) {
            const float* slot = (v == 4) ? &sm[SM_S] : &sm[SM_XU + v * 2048];
            const float* Ut = g_UcatT + v * UNITS * 24;
            #pragma unroll 8
            for (int k = 0; k < UNITS; k++)
                acc += slot[k * TP + p] * Ut[k * 24 + d];
        }
        g_FP[(base + p) * DD + d] = acc;
    }
}

__global__ void epilogue_kernel(float* __restrict__ out)
{
    int warpId = threadIdx.x >> 5;
    int lane   = threadIdx.x & 31;
    int n = blockIdx.x * 8 + warpId;
    if (n >= NPT) return;

    const float* fp1 = &g_FP[n * DD];
    const float* x1r = &g_X[n * DD];
    int rp = (4096 + lane * NPT + n) * DD;
    const float* fpp = &g_FP[rp];
    const float* xp  = &g_X[rp];

    float part = 0.f;
    #pragma unroll
    for (int k = 0; k < DIMX; k++) {
        float viol = xp[k] - x1r[k];
        part += (fpp[k] - fp1[k]) * viol;
    }
    #pragma unroll
    for (int off = 16; off; off >>= 1) part += __shfl_xor_sync(0xffffffffu, part, off);

    if (lane == 0) {
        float term12 = part / (DELTAc * (float)MCc);
        float term11 = fp1[DIMX];
        #pragma unroll
        for (int k = 0; k < DIMX; k++) term11 += MUc * x1r[k] * fp1[k];
        out[n] = term11 + 0.5f * term12 - Rc * g_FVAL[n];

        const float* x2r = &g_X[(NPT + n) * DD];
        float prod = 1.f;
        #pragma unroll
        for (int k = 0; k < DIMX; k++) prod *= x2r[k];
        float payoff = powf(prod, 1.0f / (float)DIMX);
        payoff = fmaxf(payoff, 0.f);
        out[NPT + n] = g_FVAL[NPT + n] - payoff;
    }
}

extern "C" void kernel_launch(void* const* d_in, const int* in_sizes, int n_in,
                              void* d_out, int out_size)
{
    (void)in_sizes; (void)n_in; (void)out_size;
    const float* inputs = (const float*)d_in[0];
    const float* eps    = (const float*)d_in[1];
    const float* w1  = (const float*)d_in[2];
    const float* b1  = (const float*)d_in[3];
    const float* uzl = (const float*)d_in[4];
    const float* wzl = (const float*)d_in[5];
    const float* bzl = (const float*)d_in[6];
    const float* ugl = (const float*)d_in[7];
    const float* wgl = (const float*)d_in[8];
    const float* bgl = (const float*)d_in[9];
    const float* url = (const float*)d_in[10];
    const float* wrl = (const float*)d_in[11];
    const float* brl = (const float*)d_in[12];
    const float* uhl = (const float*)d_in[13];
    const float* whl = (const float*)d_in[14];
    const float* bhl = (const float*)d_in[15];
    const float* w   = (const float*)d_in[16];
    const float* b   = (const float*)d_in[17];
    float* out = (float*)d_out;

    const int smem_bytes = SM_TOT * (int)sizeof(float);
    static bool attr_set = false;
    if (!attr_set) {
        cudaFuncSetAttribute(dgm_main, cudaFuncAttributeMaxDynamicSharedMemorySize, smem_bytes);
        attr_set = true;
    }

    prep_kernel<<<64, 256>>>(wzl, wgl, wrl, whl, uzl, ugl, url, uhl, w1);
    build_kernel<<<BTOT / 256, 256>>>(inputs, eps);
    dgm_main<<<NTILES, 256, smem_bytes>>>(w1, b1, uzl, wzl, bzl, ugl, wgl, bgl,
                                          url, wrl, brl, uhl, whl, bhl, w, b);
    epilogue_kernel<<<NPT / 8, 256>>>(out);
}

// round 8
// speedup vs baseline: 1.4246x; 1.4246x over previous
#include <cuda_runtime.h>
#include <math.h>

#define DIMX   20
#define DD     21
#define NPT    2048
#define MCc    32
#define UNITS  128
#define TP     16
#define BTOT   69632
#define NTILES (BTOT / TP)
#define THREADS 512

#define SIGc   0.2f
#define MUc    0.05f
#define Rc     0.05f
#define DELTAc 0.01f

__device__ float g_L[DIMX * DIMX];
__device__ float g_WT[4 * UNITS * UNITS];      // [mat][k][j] view = W[j][k] (for backward @W^T)
__device__ float g_UcatT[5 * UNITS * 24];      // [v][j][24] : U_v[d][j] at col d
__device__ float g_X[BTOT * DD];
__device__ float g_FP[BTOT * DD];
__device__ float g_FVAL[BTOT];

// smem layout (floats)
#define SM_X    0                        // 21*16 = 336
#define SM_S    336                      // 3 * 2048
#define SM_Z    (SM_S + 3 * 2048)
#define SM_G    (SM_Z + 3 * 2048)
#define SM_R    (SM_G + 3 * 2048)
#define SM_H    (SM_R + 3 * 2048)
#define SM_FRED (SM_H + 3 * 2048)        // 64
#define SM_TOT  (SM_FRED + 64)           // 31120 floats = 124480 B

__global__ void prep_kernel(const float* __restrict__ wz, const float* __restrict__ wg,
                            const float* __restrict__ wr, const float* __restrict__ wh,
                            const float* __restrict__ uz, const float* __restrict__ ug,
                            const float* __restrict__ ur, const float* __restrict__ uh,
                            const float* __restrict__ w1)
{
    int idx = blockIdx.x * blockDim.x + threadIdx.x;
    int stride = gridDim.x * blockDim.x;

    for (int t = idx; t < 4 * UNITS * UNITS; t += stride) {
        int mat = t >> 14;
        int r   = t & 16383;
        int a   = r >> 7;     // row in transposed layout
        int b   = r & 127;
        const float* W = (mat == 0) ? wz : (mat == 1) ? wg : (mat == 2) ? wr : wh;
        g_WT[t] = W[b * UNITS + a];   // g_WT[mat][a][b] = W[b][a]
    }
    for (int t = idx; t < 5 * UNITS * DD; t += stride) {
        int v = t / (UNITS * DD);
        int r = t % (UNITS * DD);
        int j = r / DD;
        int d = r % DD;
        const float* U = (v == 0) ? uz : (v == 1) ? ug : (v == 2) ? ur : (v == 3) ? uh : w1;
        g_UcatT[(v * UNITS + j) * 24 + d] = U[d * UNITS + j];
    }
    if (idx == 0) {
        double Ld[DIMX][DIMX];
        for (int i = 0; i < DIMX; i++) {
            for (int j2 = 0; j2 <= i; j2++) {
                double s = 0.01 * (0.5 + (i == j2 ? 0.5 : 0.0));
                for (int k = 0; k < j2; k++) s -= Ld[i][k] * Ld[j2][k];
                Ld[i][j2] = (i == j2) ? sqrt(s) : s / Ld[j2][j2];
            }
        }
        for (int i = 0; i < DIMX; i++)
            for (int j2 = 0; j2 < DIMX; j2++)
                g_L[i * DIMX + j2] = (j2 <= i) ? (float)Ld[i][j2] : 0.0f;
    }
}

__global__ void build_kernel(const float* __restrict__ inputs, const float* __restrict__ eps)
{
    int r = blockIdx.x * blockDim.x + threadIdx.x;
    if (r >= BTOT) return;
    if (r < 4096) {
        #pragma unroll
        for (int d = 0; d < DD; d++) g_X[r * DD + d] = inputs[r * DD + d];
    } else {
        int q = r - 4096;
        int m = q >> 11;
        int n = q & 2047;
        float xr[DD];
        #pragma unroll
        for (int d = 0; d < DD; d++) xr[d] = inputs[n * DD + d];
        float e[DIMX];
        #pragma unroll
        for (int d = 0; d < DIMX; d++) e[d] = eps[(m * NPT + n) * DIMX + d];
        #pragma unroll
        for (int k = 0; k < DIMX; k++) {
            float acc = 0.f;
            #pragma unroll
            for (int d = 0; d < DIMX; d++) acc += e[d] * g_L[k * DIMX + d];
            float sample = xr[k] + acc;
            float viol = sample * (SIGc * xr[k]);
            g_X[r * DD + k] = xr[k] + viol;
        }
        g_X[r * DD + DIMX] = xr[DIMX];
    }
}

// ---- helpers (4 points/thread) ----
__device__ __forceinline__ void st4(float* dst, const float a[4], int j, int p0) {
    *(float4*)&dst[j * TP + p0] = make_float4(a[0], a[1], a[2], a[3]);
}
__device__ __forceinline__ void ld4v(float a[4], const float* src, int j, int p0) {
    float4 t = *(const float4*)&src[j * TP + p0];
    a[0] = t.x; a[1] = t.y; a[2] = t.z; a[3] = t.w;
}
// acc[p] += sum_k S[k][p] * W[k*128+j]   (coalesced LDG over j, broadcast LDS over lanes)
__device__ __forceinline__ void mmW(float acc[4], const float* __restrict__ W,
                                    const float* S, int j, int p0) {
    #pragma unroll 8
    for (int k = 0; k < UNITS; k++) {
        float wv = W[k * UNITS + j];
        float4 s = *(const float4*)&S[k * TP + p0];
        acc[0] += s.x * wv; acc[1] += s.y * wv; acc[2] += s.z * wv; acc[3] += s.w * wv;
    }
}
// acc[p] += sum_k (S[k][p]*R[k][p]) * W[k*128+j]
__device__ __forceinline__ void mmW_sr(float acc[4], const float* __restrict__ W,
                                       const float* S, const float* Rr, int j, int p0) {
    #pragma unroll 8
    for (int k = 0; k < UNITS; k++) {
        float wv = W[k * UNITS + j];
        float4 s = *(const float4*)&S[k * TP + p0];
        float4 r = *(const float4*)&Rr[k * TP + p0];
        acc[0] += s.x * r.x * wv; acc[1] += s.y * r.y * wv;
        acc[2] += s.z * r.z * wv; acc[3] += s.w * r.w * wv;
    }
}
// acc[p] += sum_d X[d][p] * U[d*128+j]
__device__ __forceinline__ void mmX(float acc[4], const float* __restrict__ U,
                                    const float* X, int j, int p0) {
    #pragma unroll
    for (int d = 0; d < DD; d++) {
        float wv = U[d * UNITS + j];
        float4 s = *(const float4*)&X[d * TP + p0];
        acc[0] += s.x * wv; acc[1] += s.y * wv; acc[2] += s.z * wv; acc[3] += s.w * wv;
    }
}

__global__ __launch_bounds__(THREADS, 1)
void dgm_main(const float* __restrict__ w1, const float* __restrict__ b1,
              const float* __restrict__ uz, const float* __restrict__ wz, const float* __restrict__ bz,
              const float* __restrict__ ug, const float* __restrict__ wg, const float* __restrict__ bg,
              const float* __restrict__ ur, const float* __restrict__ wr, const float* __restrict__ br,
              const float* __restrict__ uh, const float* __restrict__ wh, const float* __restrict__ bh,
              const float* __restrict__ wout, const float* __restrict__ bout)
{
    extern __shared__ float sm[];
    const int tid = threadIdx.x;
    const int j   = tid & 127;
    const int pg  = tid >> 7;       // 0..3
    const int p0  = pg * 4;
    const int base = blockIdx.x * TP;
    const bool doGrad = !(blockIdx.x >= 128 && blockIdx.x < 256);

    // load x tile as [d][p]
    for (int t = tid; t < TP * DD; t += THREADS) {
        int p = t / DD, d = t % DD;
        sm[SM_X + d * TP + p] = g_X[(base + p) * DD + d];
    }
    __syncthreads();

    // x@U + b in registers (shared across the 3 layers), plus s0
    float xz[4], xg[4], xr4[4], xh[4], s_cur[4];
    {
        float bb;
        bb = bz[j];
        #pragma unroll
        for (int p = 0; p < 4; p++) xz[p] = bb;
        mmX(xz, uz, &sm[SM_X], j, p0);
        bb = bg[j];
        #pragma unroll
        for (int p = 0; p < 4; p++) xg[p] = bb;
        mmX(xg, ug, &sm[SM_X], j, p0);
        bb = br[j];
        #pragma unroll
        for (int p = 0; p < 4; p++) xr4[p] = bb;
        mmX(xr4, ur, &sm[SM_X], j, p0);
        bb = bh[j];
        #pragma unroll
        for (int p = 0; p < 4; p++) xh[p] = bb;
        mmX(xh, uh, &sm[SM_X], j, p0);
        float acc[4];
        bb = b1[j];
        #pragma unroll
        for (int p = 0; p < 4; p++) acc[p] = bb;
        mmX(acc, w1, &sm[SM_X], j, p0);
        #pragma unroll
        for (int p = 0; p < 4; p++) s_cur[p] = tanhf(acc[p]);
        st4(&sm[SM_S + 0 * 2048], s_cur, j, p0);
    }
    __syncthreads();

    // ---- forward ----
    #pragma unroll 1
    for (int l = 0; l < 3; l++) {
        float* Sin = &sm[SM_S + l * 2048];
        float* ZA  = &sm[SM_Z + l * 2048];
        float* GA  = &sm[SM_G + l * 2048];
        float* RA  = &sm[SM_R + l * 2048];
        float* HA  = &sm[SM_H + l * 2048];

        float z4[4], g4[4], h4[4];
        {
            float acc[4] = {xz[0], xz[1], xz[2], xz[3]};
            mmW(acc, wz, Sin, j, p0);
            #pragma unroll
            for (int p = 0; p < 4; p++) z4[p] = tanhf(acc[p]);
            st4(ZA, z4, j, p0);
        }
        {
            float acc[4] = {xg[0], xg[1], xg[2], xg[3]};
            mmW(acc, wg, Sin, j, p0);
            #pragma unroll
            for (int p = 0; p < 4; p++) g4[p] = tanhf(acc[p]);
            st4(GA, g4, j, p0);
        }
        {
            float acc[4] = {xr4[0], xr4[1], xr4[2], xr4[3]};
            mmW(acc, wr, Sin, j, p0);
            float r4[4];
            #pragma unroll
            for (int p = 0; p < 4; p++) r4[p] = tanhf(acc[p]);
            st4(RA, r4, j, p0);
        }
        __syncthreads();
        {
            float acc[4] = {xh[0], xh[1], xh[2], xh[3]};
            mmW_sr(acc, wh, Sin, RA, j, p0);
            #pragma unroll
            for (int p = 0; p < 4; p++) h4[p] = tanhf(acc[p]);
            st4(HA, h4, j, p0);
        }
        #pragma unroll
        for (int p = 0; p < 4; p++)
            s_cur[p] = (1.0f - g4[p]) * h4[p] + z4[p] * s_cur[p];
        if (l < 2) {
            st4(&sm[SM_S + (l + 1) * 2048], s_cur, j, p0);
            __syncthreads();
        }
    }

    // ---- value f = s3@w + b ----
    {
        float wv = wout[j];
        int warpId = tid >> 5;
        #pragma unroll
        for (int p = 0; p < 4; p++) {
            float v = wv * s_cur[p];
            #pragma unroll
            for (int off = 16; off; off >>= 1) v += __shfl_xor_sync(0xffffffffu, v, off);
            if ((tid & 31) == 0) sm[SM_FRED + warpId * 4 + p] = v;
        }
        __syncthreads();
        if (tid < TP) {
            int p = tid;
            int pgp = p >> 2;
            float f = bout[0];
            #pragma unroll
            for (int q = 0; q < 4; q++) f += sm[SM_FRED + (pgp * 4 + q) * 4 + (p & 3)];
            g_FVAL[base + p] = f;
        }
    }

    if (!doGrad) return;

    // ---- backward ----
    float ds[4], Daz[4], Dag[4], Dar[4], Dah[4];
    {
        float wv = wout[j];
        #pragma unroll
        for (int p = 0; p < 4; p++) {
            ds[p] = wv;
            Daz[p] = 0.f; Dag[p] = 0.f; Dar[p] = 0.f; Dah[p] = 0.f;
        }
    }

    #pragma unroll 1
    for (int l = 2; l >= 0; l--) {
        float* Sin = &sm[SM_S + l * 2048];
        float* ZA  = &sm[SM_Z + l * 2048];
        float* GA  = &sm[SM_G + l * 2048];
        float* RA  = &sm[SM_R + l * 2048];
        float* HA  = &sm[SM_H + l * 2048];

        // stage A: elementwise; overwrite Z/G/H with daz/dag/dah; accumulate into regs
        {
            float z4[4], g4[4], h4[4], sl4[4];
            ld4v(z4, ZA, j, p0);
            ld4v(g4, GA, j, p0);
            ld4v(h4, HA, j, p0);
            ld4v(sl4, Sin, j, p0);
            float daz[4], dag[4], dah[4];
            #pragma unroll
            for (int p = 0; p < 4; p++) {
                float dsp = ds[p];
                float dh = dsp * (1.0f - g4[p]);
                float dg = -dsp * h4[p];
                float dz = dsp * sl4[p];
                daz[p] = dz * (1.0f - z4[p] * z4[p]);
                dag[p] = dg * (1.0f - g4[p] * g4[p]);
                dah[p] = dh * (1.0f - h4[p] * h4[p]);
                Daz[p] += daz[p]; Dag[p] += dag[p]; Dah[p] += dah[p];
                ds[p] = dsp * z4[p];
            }
            st4(ZA, daz, j, p0);
            st4(GA, dag, j, p0);
            st4(HA, dah, j, p0);
        }
        __syncthreads();

        // stage B: dsr = dah @ Wh^T
        float dsr[4] = {0.f, 0.f, 0.f, 0.f};
        mmW(dsr, g_WT + 3 * UNITS * UNITS, HA, j, p0);

        // stage C: dar; overwrite R; accumulate
        {
            float r4[4], sl4[4], dar[4];
            ld4v(r4, RA, j, p0);
            ld4v(sl4, Sin, j, p0);
            #pragma unroll
            for (int p = 0; p < 4; p++) {
                ds[p] += dsr[p] * r4[p];
                dar[p] = (dsr[p] * sl4[p]) * (1.0f - r4[p] * r4[p]);
                Dar[p] += dar[p];
            }
            st4(RA, dar, j, p0);
        }
        __syncthreads();

        // stage D: ds += daz@Wz^T + dag@Wg^T + dar@Wr^T
        {
            const float* WzT = g_WT + 0 * UNITS * UNITS;
            const float* WgT = g_WT + 1 * UNITS * UNITS;
            const float* WrT = g_WT + 2 * UNITS * UNITS;
            #pragma unroll 4
            for (int k = 0; k < UNITS; k++) {
                float az = WzT[k * UNITS + j];
                float ag = WgT[k * UNITS + j];
                float ar = WrT[k * UNITS + j];
                float4 zz = *(const float4*)&ZA[k * TP + p0];
                float4 gg = *(const float4*)&GA[k * TP + p0];
                float4 rr = *(const float4*)&RA[k * TP + p0];
                ds[0] += zz.x * az + gg.x * ag + rr.x * ar;
                ds[1] += zz.y * az + gg.y * ag + rr.y * ar;
                ds[2] += zz.z * az + gg.z * ag + rr.z * ar;
                ds[3] += zz.w * az + gg.w * ag + rr.w * ar;
            }
        }
        // stage A(l-1) writes only layer l-1 arrays at own rows: no barrier needed here
    }

    // barrier before reusing layer-0 slots as Σda outputs (others may still read them in stage D)
    __syncthreads();
    {
        float da1[4], s04[4];
        ld4v(s04, &sm[SM_S], j, p0);
        #pragma unroll
        for (int p = 0; p < 4; p++) da1[p] = ds[p] * (1.0f - s04[p] * s04[p]);
        st4(&sm[SM_Z], Daz, j, p0);
        st4(&sm[SM_G], Dag, j, p0);
        st4(&sm[SM_R], Dar, j, p0);
        st4(&sm[SM_H], Dah, j, p0);
        st4(&sm[SM_S], da1, j, p0);
    }
    __syncthreads();

    // dx = Σ_v Da_v @ U_v^T -> coalesced FP write
    if (tid < DD * TP) {
        int d = tid % DD;
        int p = tid / DD;
        float acc = 0.f;
        #pragma unroll 1
        for (int v = 0; v < 5; v++) {
            const float* slot =
                (v == 0) ? &sm[SM_Z] : (v == 1) ? &sm[SM_G] :
                (v == 2) ? &sm[SM_R] : (v == 3) ? &sm[SM_H] : &sm[SM_S];
            const float* Ut = g_UcatT + v * UNITS * 24;
            #pragma unroll 8
            for (int k = 0; k < UNITS; k++)
                acc += slot[k * TP + p] * Ut[k * 24 + d];
        }
        g_FP[base * DD + tid] = acc;   // == (base+p)*DD + d
    }
}

__global__ void epilogue_kernel(float* __restrict__ out)
{
    int warpId = threadIdx.x >> 5;
    int lane   = threadIdx.x & 31;
    int n = blockIdx.x * 8 + warpId;
    if (n >= NPT) return;

    const float* fp1 = &g_FP[n * DD];
    const float* x1r = &g_X[n * DD];
    int rp = (4096 + lane * NPT + n) * DD;
    const float* fpp = &g_FP[rp];
    const float* xp  = &g_X[rp];

    float part = 0.f;
    #pragma unroll
    for (int k = 0; k < DIMX; k++) {
        float viol = xp[k] - x1r[k];
        part += (fpp[k] - fp1[k]) * viol;
    }
    #pragma unroll
    for (int off = 16; off; off >>= 1) part += __shfl_xor_sync(0xffffffffu, part, off);

    if (lane == 0) {
        float term12 = part / (DELTAc * (float)MCc);
        float term11 = fp1[DIMX];
        #pragma unroll
        for (int k = 0; k < DIMX; k++) term11 += MUc * x1r[k] * fp1[k];
        out[n] = term11 + 0.5f * term12 - Rc * g_FVAL[n];

        const float* x2r = &g_X[(NPT + n) * DD];
        float prod = 1.f;
        #pragma unroll
        for (int k = 0; k < DIMX; k++) prod *= x2r[k];
        float payoff = powf(prod, 1.0f / (float)DIMX);
        payoff = fmaxf(payoff, 0.f);
        out[NPT + n] = g_FVAL[NPT + n] - payoff;
    }
}

extern "C" void kernel_launch(void* const* d_in, const int* in_sizes, int n_in,
                              void* d_out, int out_size)
{
    (void)in_sizes; (void)n_in; (void)out_size;
    const float* inputs = (const float*)d_in[0];
    const float* eps    = (const float*)d_in[1];
    const float* w1  = (const float*)d_in[2];
    const float* b1  = (const float*)d_in[3];
    const float* uzl = (const float*)d_in[4];
    const float* wzl = (const float*)d_in[5];
    const float* bzl = (const float*)d_in[6];
    const float* ugl = (const float*)d_in[7];
    const float* wgl = (const float*)d_in[8];
    const float* bgl = (const float*)d_in[9];
    const float* url = (const float*)d_in[10];
    const float* wrl = (const float*)d_in[11];
    const float* brl = (const float*)d_in[12];
    const float* uhl = (const float*)d_in[13];
    const float* whl = (const float*)d_in[14];
    const float* bhl = (const float*)d_in[15];
    const float* w   = (const float*)d_in[16];
    const float* b   = (const float*)d_in[17];
    float* out = (float*)d_out;

    const int smem_bytes = SM_TOT * (int)sizeof(float);
    static bool attr_set = false;
    if (!attr_set) {
        cudaFuncSetAttribute(dgm_main, cudaFuncAttributeMaxDynamicSharedMemorySize, smem_bytes);
        attr_set = true;
    }

    prep_kernel<<<64, 256>>>(wzl, wgl, wrl, whl, uzl, ugl, url, uhl, w1);
    build_kernel<<<BTOT / 256, 256>>>(inputs, eps);
    dgm_main<<<NTILES, THREADS, smem_bytes>>>(w1, b1, uzl, wzl, bzl, ugl, wgl, bgl,
                                              url, wrl, brl, uhl, whl, bhl, w, b);
    epilogue_kernel<<<NPT / 8, 256>>>(out);
}

// round 9
// speedup vs baseline: 1.6511x; 1.1590x over previous
#include <cuda_runtime.h>
#include <math.h>

#define DIMX   20
#define DD     21
#define NPT    2048
#define MCc    32
#define UNITS  128
#define TP     16
#define BTOT   69632
#define NTILES (BTOT / TP)
#define THREADS 512

#define SIGc   0.2f
#define MUc    0.05f
#define Rc     0.05f
#define DELTAc 0.01f

__device__ float g_L[DIMX * DIMX];
__device__ float g_WT[4 * UNITS * UNITS];      // [mat][a][b] = W[b][a]
__device__ float g_UcatT[5 * UNITS * 24];
__device__ float g_X[BTOT * DD];
__device__ float g_FP[BTOT * DD];
__device__ float g_FVAL[BTOT];

// smem layout (floats)
#define SM_X    0                        // 336
#define SM_S    336                      // 3 * 2048
#define SM_Z    (SM_S + 3 * 2048)
#define SM_G    (SM_Z + 3 * 2048)
#define SM_R    (SM_G + 3 * 2048)
#define SM_H    (SM_R + 3 * 2048)
#define SM_SR   (SM_H + 3 * 2048)        // 2048 scratch (s*r)
#define SM_FRED (SM_SR + 2048)           // 64
#define SM_TOT  (SM_FRED + 64)           // 33168 floats = 132672 B

typedef unsigned long long u64t;

__device__ __forceinline__ u64t pack2(float lo, float hi) {
    u64t r;
    asm("mov.b64 %0, {%1, %2};" : "=l"(r) : "f"(lo), "f"(hi));
    return r;
}
__device__ __forceinline__ float2 unpack2(u64t v) {
    float2 f;
    asm("mov.b64 {%0, %1}, %2;" : "=f"(f.x), "=f"(f.y) : "l"(v));
    return f;
}
__device__ __forceinline__ u64t ffma2(u64t a, u64t b, u64t c) {
    u64t d;
    asm("fma.rn.f32x2 %0, %1, %2, %3;" : "=l"(d) : "l"(a), "l"(b), "l"(c));
    return d;
}

__device__ __forceinline__ float ftanh(float x) {
    float ax = fabsf(x);
    float t = __expf(-2.0f * ax);
    float r = __fdividef(1.0f - t, 1.0f + t);
    return copysignf(r, x);
}

__global__ void prep_kernel(const float* __restrict__ wz, const float* __restrict__ wg,
                            const float* __restrict__ wr, const float* __restrict__ wh,
                            const float* __restrict__ uz, const float* __restrict__ ug,
                            const float* __restrict__ ur, const float* __restrict__ uh,
                            const float* __restrict__ w1)
{
    int idx = blockIdx.x * blockDim.x + threadIdx.x;
    int stride = gridDim.x * blockDim.x;

    for (int t = idx; t < 4 * UNITS * UNITS; t += stride) {
        int mat = t >> 14;
        int r   = t & 16383;
        int a   = r >> 7;
        int b   = r & 127;
        const float* W = (mat == 0) ? wz : (mat == 1) ? wg : (mat == 2) ? wr : wh;
        g_WT[t] = W[b * UNITS + a];
    }
    for (int t = idx; t < 5 * UNITS * DD; t += stride) {
        int v = t / (UNITS * DD);
        int r = t % (UNITS * DD);
        int j = r / DD;
        int d = r % DD;
        const float* U = (v == 0) ? uz : (v == 1) ? ug : (v == 2) ? ur : (v == 3) ? uh : w1;
        g_UcatT[(v * UNITS + j) * 24 + d] = U[d * UNITS + j];
    }
    if (idx == 0) {
        double Ld[DIMX][DIMX];
        for (int i = 0; i < DIMX; i++) {
            for (int j2 = 0; j2 <= i; j2++) {
                double s = 0.01 * (0.5 + (i == j2 ? 0.5 : 0.0));
                for (int k = 0; k < j2; k++) s -= Ld[i][k] * Ld[j2][k];
                Ld[i][j2] = (i == j2) ? sqrt(s) : s / Ld[j2][j2];
            }
        }
        for (int i = 0; i < DIMX; i++)
            for (int j2 = 0; j2 < DIMX; j2++)
                g_L[i * DIMX + j2] = (j2 <= i) ? (float)Ld[i][j2] : 0.0f;
    }
}

__global__ void build_kernel(const float* __restrict__ inputs, const float* __restrict__ eps)
{
    int r = blockIdx.x * blockDim.x + threadIdx.x;
    if (r >= BTOT) return;
    if (r < 4096) {
        #pragma unroll
        for (int d = 0; d < DD; d++) g_X[r * DD + d] = inputs[r * DD + d];
    } else {
        int q = r - 4096;
        int m = q >> 11;
        int n = q & 2047;
        float xr[DD];
        #pragma unroll
        for (int d = 0; d < DD; d++) xr[d] = inputs[n * DD + d];
        float e[DIMX];
        #pragma unroll
        for (int d = 0; d < DIMX; d++) e[d] = eps[(m * NPT + n) * DIMX + d];
        #pragma unroll
        for (int k = 0; k < DIMX; k++) {
            float acc = 0.f;
            #pragma unroll
            for (int d = 0; d < DIMX; d++) acc += e[d] * g_L[k * DIMX + d];
            float sample = xr[k] + acc;
            float viol = sample * (SIGc * xr[k]);
            g_X[r * DD + k] = xr[k] + viol;
        }
        g_X[r * DD + DIMX] = xr[DIMX];
    }
}

// ---- helpers ----
__device__ __forceinline__ void st4(float* dst, const float a[4], int j, int p0) {
    *(float4*)&dst[j * TP + p0] = make_float4(a[0], a[1], a[2], a[3]);
}
__device__ __forceinline__ void ld4v(float a[4], const float* src, int j, int p0) {
    float4 t = *(const float4*)&src[j * TP + p0];
    a[0] = t.x; a[1] = t.y; a[2] = t.z; a[3] = t.w;
}
// scalar x@U (only 21 iterations)
__device__ __forceinline__ void mmX(float acc[4], const float* __restrict__ U,
                                    const float* X, int j, int p0) {
    #pragma unroll
    for (int d = 0; d < DD; d++) {
        float wv = U[d * UNITS + j];
        float4 s = *(const float4*)&X[d * TP + p0];
        acc[0] += s.x * wv; acc[1] += s.y * wv; acc[2] += s.z * wv; acc[3] += s.w * wv;
    }
}
// single-matrix packed matmul: a01/a23 += S_pair * {w,w}
__device__ __forceinline__ void mmW2(u64t& a01, u64t& a23, const float* __restrict__ W,
                                     const float* S, int j, int p0) {
    #pragma unroll 8
    for (int k = 0; k < UNITS; k++) {
        float wv = W[k * UNITS + j];
        u64t wp = pack2(wv, wv);
        ulonglong2 s = *(const ulonglong2*)&S[k * TP + p0];
        a01 = ffma2(s.x, wp, a01);
        a23 = ffma2(s.y, wp, a23);
    }
}

__global__ __launch_bounds__(THREADS, 1)
void dgm_main(const float* __restrict__ w1, const float* __restrict__ b1,
              const float* __restrict__ uz, const float* __restrict__ wz, const float* __restrict__ bz,
              const float* __restrict__ ug, const float* __restrict__ wg, const float* __restrict__ bg,
              const float* __restrict__ ur, const float* __restrict__ wr, const float* __restrict__ br,
              const float* __restrict__ uh, const float* __restrict__ wh, const float* __restrict__ bh,
              const float* __restrict__ wout, const float* __restrict__ bout)
{
    extern __shared__ float sm[];
    const int tid = threadIdx.x;
    const int j   = tid & 127;
    const int pg  = tid >> 7;
    const int p0  = pg * 4;
    const int base = blockIdx.x * TP;
    const bool doGrad = !(blockIdx.x >= 128 && blockIdx.x < 256);

    for (int t = tid; t < TP * DD; t += THREADS) {
        int p = t / DD, d = t % DD;
        sm[SM_X + d * TP + p] = g_X[(base + p) * DD + d];
    }
    __syncthreads();

    // x@U + b in registers, and s0
    float xz[4], xg[4], xr4[4], xh[4], s_cur[4];
    {
        float bb;
        bb = bz[j];
        #pragma unroll
        for (int p = 0; p < 4; p++) xz[p] = bb;
        mmX(xz, uz, &sm[SM_X], j, p0);
        bb = bg[j];
        #pragma unroll
        for (int p = 0; p < 4; p++) xg[p] = bb;
        mmX(xg, ug, &sm[SM_X], j, p0);
        bb = br[j];
        #pragma unroll
        for (int p = 0; p < 4; p++) xr4[p] = bb;
        mmX(xr4, ur, &sm[SM_X], j, p0);
        bb = bh[j];
        #pragma unroll
        for (int p = 0; p < 4; p++) xh[p] = bb;
        mmX(xh, uh, &sm[SM_X], j, p0);
        float acc[4];
        bb = b1[j];
        #pragma unroll
        for (int p = 0; p < 4; p++) acc[p] = bb;
        mmX(acc, w1, &sm[SM_X], j, p0);
        #pragma unroll
        for (int p = 0; p < 4; p++) s_cur[p] = ftanh(acc[p]);
        st4(&sm[SM_S + 0 * 2048], s_cur, j, p0);
    }
    __syncthreads();

    // ---- forward ----
    #pragma unroll 1
    for (int l = 0; l < 3; l++) {
        float* Sin = &sm[SM_S + l * 2048];
        float* ZA  = &sm[SM_Z + l * 2048];
        float* GA  = &sm[SM_G + l * 2048];
        float* RA  = &sm[SM_R + l * 2048];
        float* HA  = &sm[SM_H + l * 2048];
        float* SR  = &sm[SM_SR];

        float z4[4], g4[4], h4[4];
        // merged z/g/r matmul: one LDS of S shared by 3 weight streams, f32x2 FMAs
        {
            u64t az0 = pack2(xz[0], xz[1]), az1 = pack2(xz[2], xz[3]);
            u64t ag0 = pack2(xg[0], xg[1]), ag1 = pack2(xg[2], xg[3]);
            u64t ar0 = pack2(xr4[0], xr4[1]), ar1 = pack2(xr4[2], xr4[3]);
            #pragma unroll 4
            for (int k = 0; k < UNITS; k++) {
                float wzv = wz[k * UNITS + j];
                float wgv = wg[k * UNITS + j];
                float wrv = wr[k * UNITS + j];
                u64t wzp = pack2(wzv, wzv);
                u64t wgp = pack2(wgv, wgv);
                u64t wrp = pack2(wrv, wrv);
                ulonglong2 s = *(const ulonglong2*)&Sin[k * TP + p0];
                az0 = ffma2(s.x, wzp, az0); az1 = ffma2(s.y, wzp, az1);
                ag0 = ffma2(s.x, wgp, ag0); ag1 = ffma2(s.y, wgp, ag1);
                ar0 = ffma2(s.x, wrp, ar0); ar1 = ffma2(s.y, wrp, ar1);
            }
            float2 t0, t1;
            float r4[4], sr4[4];
            t0 = unpack2(az0); t1 = unpack2(az1);
            z4[0] = ftanh(t0.x); z4[1] = ftanh(t0.y); z4[2] = ftanh(t1.x); z4[3] = ftanh(t1.y);
            t0 = unpack2(ag0); t1 = unpack2(ag1);
            g4[0] = ftanh(t0.x); g4[1] = ftanh(t0.y); g4[2] = ftanh(t1.x); g4[3] = ftanh(t1.y);
            t0 = unpack2(ar0); t1 = unpack2(ar1);
            r4[0] = ftanh(t0.x); r4[1] = ftanh(t0.y); r4[2] = ftanh(t1.x); r4[3] = ftanh(t1.y);
            st4(ZA, z4, j, p0);
            st4(GA, g4, j, p0);
            st4(RA, r4, j, p0);
            #pragma unroll
            for (int p = 0; p < 4; p++) sr4[p] = s_cur[p] * r4[p];
            st4(SR, sr4, j, p0);
        }
        __syncthreads();
        // h matmul over SR
        {
            u64t ah0 = pack2(xh[0], xh[1]), ah1 = pack2(xh[2], xh[3]);
            mmW2(ah0, ah1, wh, SR, j, p0);
            float2 t0 = unpack2(ah0), t1 = unpack2(ah1);
            h4[0] = ftanh(t0.x); h4[1] = ftanh(t0.y); h4[2] = ftanh(t1.x); h4[3] = ftanh(t1.y);
            st4(HA, h4, j, p0);
        }
        #pragma unroll
        for (int p = 0; p < 4; p++)
            s_cur[p] = (1.0f - g4[p]) * h4[p] + z4[p] * s_cur[p];
        if (l < 2) {
            st4(&sm[SM_S + (l + 1) * 2048], s_cur, j, p0);
        }
        __syncthreads();
    }

    // ---- value f = s3@w + b ----
    {
        float wv = wout[j];
        int warpId = tid >> 5;
        #pragma unroll
        for (int p = 0; p < 4; p++) {
            float v = wv * s_cur[p];
            #pragma unroll
            for (int off = 16; off; off >>= 1) v += __shfl_xor_sync(0xffffffffu, v, off);
            if ((tid & 31) == 0) sm[SM_FRED + warpId * 4 + p] = v;
        }
        __syncthreads();
        if (tid < TP) {
            int p = tid;
            int pgp = p >> 2;
            float f = bout[0];
            #pragma unroll
            for (int q = 0; q < 4; q++) f += sm[SM_FRED + (pgp * 4 + q) * 4 + (p & 3)];
            g_FVAL[base + p] = f;
        }
    }

    if (!doGrad) return;

    // ---- backward ----
    float ds[4], Daz[4], Dag[4], Dar[4], Dah[4];
    {
        float wv = wout[j];
        #pragma unroll
        for (int p = 0; p < 4; p++) {
            ds[p] = wv;
            Daz[p] = 0.f; Dag[p] = 0.f; Dar[p] = 0.f; Dah[p] = 0.f;
        }
    }

    #pragma unroll 1
    for (int l = 2; l >= 0; l--) {
        float* Sin = &sm[SM_S + l * 2048];
        float* ZA  = &sm[SM_Z + l * 2048];
        float* GA  = &sm[SM_G + l * 2048];
        float* RA  = &sm[SM_R + l * 2048];
        float* HA  = &sm[SM_H + l * 2048];

        // stage A
        {
            float z4[4], g4[4], h4[4], sl4[4];
            ld4v(z4, ZA, j, p0);
            ld4v(g4, GA, j, p0);
            ld4v(h4, HA, j, p0);
            ld4v(sl4, Sin, j, p0);
            float daz[4], dag[4], dah[4];
            #pragma unroll
            for (int p = 0; p < 4; p++) {
                float dsp = ds[p];
                float dh = dsp * (1.0f - g4[p]);
                float dg = -dsp * h4[p];
                float dz = dsp * sl4[p];
                daz[p] = dz * (1.0f - z4[p] * z4[p]);
                dag[p] = dg * (1.0f - g4[p] * g4[p]);
                dah[p] = dh * (1.0f - h4[p] * h4[p]);
                Daz[p] += daz[p]; Dag[p] += dag[p]; Dah[p] += dah[p];
                ds[p] = dsp * z4[p];
            }
            st4(ZA, daz, j, p0);
            st4(GA, dag, j, p0);
            st4(HA, dah, j, p0);
        }
        __syncthreads();

        // stage B: dsr = dah @ Wh^T (packed)
        float dsr[4];
        {
            u64t b0 = pack2(0.f, 0.f), b1p = pack2(0.f, 0.f);
            mmW2(b0, b1p, g_WT + 3 * UNITS * UNITS, HA, j, p0);
            float2 t0 = unpack2(b0), t1 = unpack2(b1p);
            dsr[0] = t0.x; dsr[1] = t0.y; dsr[2] = t1.x; dsr[3] = t1.y;
        }

        // stage C
        {
            float r4[4], sl4[4], dar[4];
            ld4v(r4, RA, j, p0);
            ld4v(sl4, Sin, j, p0);
            #pragma unroll
            for (int p = 0; p < 4; p++) {
                ds[p] += dsr[p] * r4[p];
                dar[p] = (dsr[p] * sl4[p]) * (1.0f - r4[p] * r4[p]);
                Dar[p] += dar[p];
            }
            st4(RA, dar, j, p0);
        }
        __syncthreads();

        // stage D: ds += daz@Wz^T + dag@Wg^T + dar@Wr^T (merged, packed)
        {
            const float* WzT = g_WT + 0 * UNITS * UNITS;
            const float* WgT = g_WT + 1 * UNITS * UNITS;
            const float* WrT = g_WT + 2 * UNITS * UNITS;
            u64t d0 = pack2(ds[0], ds[1]), d1 = pack2(ds[2], ds[3]);
            #pragma unroll 4
            for (int k = 0; k < UNITS; k++) {
                float az = WzT[k * UNITS + j];
                float ag = WgT[k * UNITS + j];
                float ar = WrT[k * UNITS + j];
                u64t azp = pack2(az, az);
                u64t agp = pack2(ag, ag);
                u64t arp = pack2(ar, ar);
                ulonglong2 zz = *(const ulonglong2*)&ZA[k * TP + p0];
                ulonglong2 gg = *(const ulonglong2*)&GA[k * TP + p0];
                ulonglong2 rr = *(const ulonglong2*)&RA[k * TP + p0];
                d0 = ffma2(zz.x, azp, d0); d1 = ffma2(zz.y, azp, d1);
                d0 = ffma2(gg.x, agp, d0); d1 = ffma2(gg.y, agp, d1);
                d0 = ffma2(rr.x, arp, d0); d1 = ffma2(rr.y, arp, d1);
            }
            float2 t0 = unpack2(d0), t1 = unpack2(d1);
            ds[0] = t0.x; ds[1] = t0.y; ds[2] = t1.x; ds[3] = t1.y;
        }
        // next stage A writes only layer l-1 arrays at own rows: no barrier needed
    }

    __syncthreads();
    {
        float da1[4], s04[4];
        ld4v(s04, &sm[SM_S], j, p0);
        #pragma unroll
        for (int p = 0; p < 4; p++) da1[p] = ds[p] * (1.0f - s04[p] * s04[p]);
        st4(&sm[SM_Z], Daz, j, p0);
        st4(&sm[SM_G], Dag, j, p0);
        st4(&sm[SM_R], Dar, j, p0);
        st4(&sm[SM_H], Dah, j, p0);
        st4(&sm[SM_S], da1, j, p0);
    }
    __syncthreads();

    // dx = Σ_v Da_v @ U_v^T -> coalesced FP write
    if (tid < DD * TP) {
        int d = tid % DD;
        int p = tid / DD;
        float acc = 0.f;
        #pragma unroll 1
        for (int v = 0; v < 5; v++) {
            const float* slot =
                (v == 0) ? &sm[SM_Z] : (v == 1) ? &sm[SM_G] :
                (v == 2) ? &sm[SM_R] : (v == 3) ? &sm[SM_H] : &sm[SM_S];
            const float* Ut = g_UcatT + v * UNITS * 24;
            #pragma unroll 8
            for (int k = 0; k < UNITS; k++)
                acc += slot[k * TP + p] * Ut[k * 24 + d];
        }
        g_FP[base * DD + tid] = acc;
    }
}

__global__ void epilogue_kernel(float* __restrict__ out)
{
    int warpId = threadIdx.x >> 5;
    int lane   = threadIdx.x & 31;
    int n = blockIdx.x * 8 + warpId;
    if (n >= NPT) return;

    const float* fp1 = &g_FP[n * DD];
    const float* x1r = &g_X[n * DD];
    int rp = (4096 + lane * NPT + n) * DD;
    const float* fpp = &g_FP[rp];
    const float* xp  = &g_X[rp];

    float part = 0.f;
    #pragma unroll
    for (int k = 0; k < DIMX; k++) {
        float viol = xp[k] - x1r[k];
        part += (fpp[k] - fp1[k]) * viol;
    }
    #pragma unroll
    for (int off = 16; off; off >>= 1) part += __shfl_xor_sync(0xffffffffu, part, off);

    if (lane == 0) {
        float term12 = part / (DELTAc * (float)MCc);
        float term11 = fp1[DIMX];
        #pragma unroll
        for (int k = 0; k < DIMX; k++) term11 += MUc * x1r[k] * fp1[k];
        out[n] = term11 + 0.5f * term12 - Rc * g_FVAL[n];

        const float* x2r = &g_X[(NPT + n) * DD];
        float prod = 1.f;
        #pragma unroll
        for (int k = 0; k < DIMX; k++) prod *= x2r[k];
        float payoff = powf(prod, 1.0f / (float)DIMX);
        payoff = fmaxf(payoff, 0.f);
        out[NPT + n] = g_FVAL[NPT + n] - payoff;
    }
}

extern "C" void kernel_launch(void* const* d_in, const int* in_sizes, int n_in,
                              void* d_out, int out_size)
{
    (void)in_sizes; (void)n_in; (void)out_size;
    const float* inputs = (const float*)d_in[0];
    const float* eps    = (const float*)d_in[1];
    const float* w1  = (const float*)d_in[2];
    const float* b1  = (const float*)d_in[3];
    const float* uzl = (const float*)d_in[4];
    const float* wzl = (const float*)d_in[5];
    const float* bzl = (const float*)d_in[6];
    const float* ugl = (const float*)d_in[7];
    const float* wgl = (const float*)d_in[8];
    const float* bgl = (const float*)d_in[9];
    const float* url = (const float*)d_in[10];
    const float* wrl = (const float*)d_in[11];
    const float* brl = (const float*)d_in[12];
    const float* uhl = (const float*)d_in[13];
    const float* whl = (const float*)d_in[14];
    const float* bhl = (const float*)d_in[15];
    const float* w   = (const float*)d_in[16];
    const float* b   = (const float*)d_in[17];
    float* out = (float*)d_out;

    const int smem_bytes = SM_TOT * (int)sizeof(float);
    static bool attr_set = false;
    if (!attr_set) {
        cudaFuncSetAttribute(dgm_main, cudaFuncAttributeMaxDynamicSharedMemorySize, smem_bytes);
        attr_set = true;
    }

    prep_kernel<<<64, 256>>>(wzl, wgl, wrl, whl, uzl, ugl, url, uhl, w1);
    build_kernel<<<BTOT / 256, 256>>>(inputs, eps);
    dgm_main<<<NTILES, THREADS, smem_bytes>>>(w1, b1, uzl, wzl, bzl, ugl, wgl, bgl,
                                              url, wrl, brl, uhl, whl, bhl, w, b);
    epilogue_kernel<<<NPT / 8, 256>>>(out);
}

// round 10
// speedup vs baseline: 1.6625x; 1.0069x over previous
#include <cuda_runtime.h>
#include <math.h>

#define DIMX   20
#define DD     21
#define NPT    2048
#define MCc    32
#define UNITS  128
#define TP     16
#define BTOT   69632
#define NTILES (BTOT / TP)
#define THREADS 256

#define SIGc   0.2f
#define MUc    0.05f
#define Rc     0.05f
#define DELTAc 0.01f

__device__ float g_L[DIMX * DIMX];
__device__ float g_WT[4 * UNITS * UNITS];   // [mat][a][b] = W[b][a]
__device__ float g_UcatT[5 * UNITS * 24];   // [v][j][24] : U_v[d][j] at col d (stride 24, padded)
__device__ float g_X[BTOT * DD];
__device__ float g_FP[BTOT * DD];
__device__ float g_FVAL[BTOT];

// smem (floats). Activation arrays are [point][unit] = [16][128] (stride 128).
#define SM_X    0                        // [21][16] = 336
#define SM_S    336                      // 3 * 2048
#define SM_Z    (SM_S + 3 * 2048)
#define SM_G    (SM_Z + 3 * 2048)
#define SM_R    (SM_G + 3 * 2048)
#define SM_H    (SM_R + 3 * 2048)
#define SM_SR   (SM_H + 3 * 2048)        // 2048 scratch
#define SM_TOT  (SM_SR + 2048)           // 33104 floats = 132416 B

typedef unsigned long long u64t;

__device__ __forceinline__ u64t pack2(float lo, float hi) {
    u64t r;
    asm("mov.b64 %0, {%1, %2};" : "=l"(r) : "f"(lo), "f"(hi));
    return r;
}
__device__ __forceinline__ float2 unpack2(u64t v) {
    float2 f;
    asm("mov.b64 {%0, %1}, %2;" : "=f"(f.x), "=f"(f.y) : "l"(v));
    return f;
}
__device__ __forceinline__ u64t ffma2(u64t a, u64t b, u64t c) {
    u64t d;
    asm("fma.rn.f32x2 %0, %1, %2, %3;" : "=l"(d) : "l"(a), "l"(b), "l"(c));
    return d;
}
__device__ __forceinline__ float ftanh(float x) {
    float ax = fabsf(x);
    float t = __expf(-2.0f * ax);
    float r = __fdividef(1.0f - t, 1.0f + t);
    return copysignf(r, x);
}

__global__ void prep_kernel(const float* __restrict__ wz, const float* __restrict__ wg,
                            const float* __restrict__ wr, const float* __restrict__ wh,
                            const float* __restrict__ uz, const float* __restrict__ ug,
                            const float* __restrict__ ur, const float* __restrict__ uh,
                            const float* __restrict__ w1)
{
    int idx = blockIdx.x * blockDim.x + threadIdx.x;
    int stride = gridDim.x * blockDim.x;

    for (int t = idx; t < 4 * UNITS * UNITS; t += stride) {
        int mat = t >> 14;
        int r   = t & 16383;
        int a   = r >> 7;
        int b   = r & 127;
        const float* W = (mat == 0) ? wz : (mat == 1) ? wg : (mat == 2) ? wr : wh;
        g_WT[t] = W[b * UNITS + a];
    }
    for (int t = idx; t < 5 * UNITS * 24; t += stride) {
        int v = t / (UNITS * 24);
        int r = t % (UNITS * 24);
        int j = r / 24;
        int d = r % 24;
        const float* U = (v == 0) ? uz : (v == 1) ? ug : (v == 2) ? ur : (v == 3) ? uh : w1;
        g_UcatT[t] = (d < DD) ? U[d * UNITS + j] : 0.0f;
    }
    if (idx == 0) {
        double Ld[DIMX][DIMX];
        for (int i = 0; i < DIMX; i++) {
            for (int j2 = 0; j2 <= i; j2++) {
                double s = 0.01 * (0.5 + (i == j2 ? 0.5 : 0.0));
                for (int k = 0; k < j2; k++) s -= Ld[i][k] * Ld[j2][k];
                Ld[i][j2] = (i == j2) ? sqrt(s) : s / Ld[j2][j2];
            }
        }
        for (int i = 0; i < DIMX; i++)
            for (int j2 = 0; j2 < DIMX; j2++)
                g_L[i * DIMX + j2] = (j2 <= i) ? (float)Ld[i][j2] : 0.0f;
    }
}

__global__ void build_kernel(const float* __restrict__ inputs, const float* __restrict__ eps)
{
    int r = blockIdx.x * blockDim.x + threadIdx.x;
    if (r >= BTOT) return;
    if (r < 4096) {
        #pragma unroll
        for (int d = 0; d < DD; d++) g_X[r * DD + d] = inputs[r * DD + d];
    } else {
        int q = r - 4096;
        int m = q >> 11;
        int n = q & 2047;
        float xr[DD];
        #pragma unroll
        for (int d = 0; d < DD; d++) xr[d] = inputs[n * DD + d];
        float e[DIMX];
        #pragma unroll
        for (int d = 0; d < DIMX; d++) e[d] = eps[(m * NPT + n) * DIMX + d];
        #pragma unroll
        for (int k = 0; k < DIMX; k++) {
            float acc = 0.f;
            #pragma unroll
            for (int d = 0; d < DIMX; d++) acc += e[d] * g_L[k * DIMX + d];
            float sample = xr[k] + acc;
            float viol = sample * (SIGc * xr[k]);
            g_X[r * DD + k] = xr[k] + viol;
        }
        g_X[r * DD + DIMX] = xr[DIMX];
    }
}

__global__ __launch_bounds__(THREADS, 1)
void dgm_main(const float* __restrict__ w1, const float* __restrict__ b1,
              const float* __restrict__ uz, const float* __restrict__ wz, const float* __restrict__ bz,
              const float* __restrict__ ug, const float* __restrict__ wg, const float* __restrict__ bg,
              const float* __restrict__ ur, const float* __restrict__ wr, const float* __restrict__ br,
              const float* __restrict__ uh, const float* __restrict__ wh, const float* __restrict__ bh,
              const float* __restrict__ wout, const float* __restrict__ bout)
{
    extern __shared__ float sm[];
    const int tid  = threadIdx.x;
    const int lane = tid & 31;
    const int j4   = lane * 4;          // 4 consecutive units
    const int pgi  = tid >> 5;          // warp id == point group
    const int p0   = pgi * 2;           // 2 points
    const int base = blockIdx.x * TP;
    const bool doGrad = !(blockIdx.x >= 128 && blockIdx.x < 256);

    // X tile [d][p]
    for (int t = tid; t < TP * DD; t += THREADS) {
        int p = t / DD, d = t % DD;
        sm[SM_X + d * TP + p] = g_X[(base + p) * DD + d];
    }
    __syncthreads();

    // ---- prologue: x@U + b for 5 matrices; accumulators [q] with q = pair*2 + pt ----
    u64t xzr[4], xgr[4], xrr[4], xhr[4], a1[4];
    {
        float4 b;
        b = *(const float4*)&bz[j4]; xzr[0] = xzr[1] = pack2(b.x, b.y); xzr[2] = xzr[3] = pack2(b.z, b.w);
        b = *(const float4*)&bg[j4]; xgr[0] = xgr[1] = pack2(b.x, b.y); xgr[2] = xgr[3] = pack2(b.z, b.w);
        b = *(const float4*)&br[j4]; xrr[0] = xrr[1] = pack2(b.x, b.y); xrr[2] = xrr[3] = pack2(b.z, b.w);
        b = *(const float4*)&bh[j4]; xhr[0] = xhr[1] = pack2(b.x, b.y); xhr[2] = xhr[3] = pack2(b.z, b.w);
        float b1v = b1[0 + j4]; float b1y = b1[j4 + 1]; float b1z = b1[j4 + 2]; float b1w = b1[j4 + 3];
        a1[0] = a1[1] = pack2(b1v, b1y); a1[2] = a1[3] = pack2(b1z, b1w);
        #pragma unroll 3
        for (int d = 0; d < DD; d++) {
            float2 xv = *(const float2*)&sm[SM_X + d * TP + p0];
            u64t x0 = pack2(xv.x, xv.x), x1 = pack2(xv.y, xv.y);
            ulonglong2 u;
            u = *(const ulonglong2*)&uz[d * UNITS + j4];
            xzr[0] = ffma2(u.x, x0, xzr[0]); xzr[1] = ffma2(u.x, x1, xzr[1]);
            xzr[2] = ffma2(u.y, x0, xzr[2]); xzr[3] = ffma2(u.y, x1, xzr[3]);
            u = *(const ulonglong2*)&ug[d * UNITS + j4];
            xgr[0] = ffma2(u.x, x0, xgr[0]); xgr[1] = ffma2(u.x, x1, xgr[1]);
            xgr[2] = ffma2(u.y, x0, xgr[2]); xgr[3] = ffma2(u.y, x1, xgr[3]);
            u = *(const ulonglong2*)&ur[d * UNITS + j4];
            xrr[0] = ffma2(u.x, x0, xrr[0]); xrr[1] = ffma2(u.x, x1, xrr[1]);
            xrr[2] = ffma2(u.y, x0, xrr[2]); xrr[3] = ffma2(u.y, x1, xrr[3]);
            u = *(const ulonglong2*)&uh[d * UNITS + j4];
            xhr[0] = ffma2(u.x, x0, xhr[0]); xhr[1] = ffma2(u.x, x1, xhr[1]);
            xhr[2] = ffma2(u.y, x0, xhr[2]); xhr[3] = ffma2(u.y, x1, xhr[3]);
            u = *(const ulonglong2*)&w1[d * UNITS + j4];
            a1[0] = ffma2(u.x, x0, a1[0]); a1[1] = ffma2(u.x, x1, a1[1]);
            a1[2] = ffma2(u.y, x0, a1[2]); a1[3] = ffma2(u.y, x1, a1[3]);
        }
    }
    float s_cur[4][2];   // [unit][pt]
    {
        #pragma unroll
        for (int q = 0; q < 4; q++) {
            float2 t = unpack2(a1[q]);
            int u0 = (q >> 1) * 2, pt = q & 1;
            s_cur[u0][pt]     = ftanh(t.x);
            s_cur[u0 + 1][pt] = ftanh(t.y);
        }
        #pragma unroll
        for (int pt = 0; pt < 2; pt++)
            *(float4*)&sm[SM_S + (p0 + pt) * UNITS + j4] =
                make_float4(s_cur[0][pt], s_cur[1][pt], s_cur[2][pt], s_cur[3][pt]);
    }
    __syncthreads();

    // ---- forward ----
    #pragma unroll 1
    for (int l = 0; l < 3; l++) {
        float* Sin = &sm[SM_S + l * 2048];
        float* ZA  = &sm[SM_Z + l * 2048];
        float* GA  = &sm[SM_G + l * 2048];
        float* RA  = &sm[SM_R + l * 2048];
        float* HA  = &sm[SM_H + l * 2048];
        float* SR  = &sm[SM_SR];

        u64t az[4] = {xzr[0], xzr[1], xzr[2], xzr[3]};
        u64t ag[4] = {xgr[0], xgr[1], xgr[2], xgr[3]};
        u64t ar[4] = {xrr[0], xrr[1], xrr[2], xrr[3]};
        #pragma unroll 4
        for (int k = 0; k < UNITS; k++) {
            ulonglong2 wz2 = *(const ulonglong2*)&wz[k * UNITS + j4];
            ulonglong2 wg2 = *(const ulonglong2*)&wg[k * UNITS + j4];
            ulonglong2 wr2 = *(const ulonglong2*)&wr[k * UNITS + j4];
            float sv0 = Sin[p0 * UNITS + k];
            float sv1 = Sin[(p0 + 1) * UNITS + k];
            u64t s0p = pack2(sv0, sv0), s1p = pack2(sv1, sv1);
            az[0] = ffma2(wz2.x, s0p, az[0]); az[1] = ffma2(wz2.x, s1p, az[1]);
            az[2] = ffma2(wz2.y, s0p, az[2]); az[3] = ffma2(wz2.y, s1p, az[3]);
            ag[0] = ffma2(wg2.x, s0p, ag[0]); ag[1] = ffma2(wg2.x, s1p, ag[1]);
            ag[2] = ffma2(wg2.y, s0p, ag[2]); ag[3] = ffma2(wg2.y, s1p, ag[3]);
            ar[0] = ffma2(wr2.x, s0p, ar[0]); ar[1] = ffma2(wr2.x, s1p, ar[1]);
            ar[2] = ffma2(wr2.y, s0p, ar[2]); ar[3] = ffma2(wr2.y, s1p, ar[3]);
        }
        float z4[4][2], g4[4][2], r4[4][2];
        #pragma unroll
        for (int q = 0; q < 4; q++) {
            int u0 = (q >> 1) * 2, pt = q & 1;
            float2 t;
            t = unpack2(az[q]); z4[u0][pt] = ftanh(t.x); z4[u0 + 1][pt] = ftanh(t.y);
            t = unpack2(ag[q]); g4[u0][pt] = ftanh(t.x); g4[u0 + 1][pt] = ftanh(t.y);
            t = unpack2(ar[q]); r4[u0][pt] = ftanh(t.x); r4[u0 + 1][pt] = ftanh(t.y);
        }
        #pragma unroll
        for (int pt = 0; pt < 2; pt++) {
            int row = (p0 + pt) * UNITS + j4;
            *(float4*)&ZA[row] = make_float4(z4[0][pt], z4[1][pt], z4[2][pt], z4[3][pt]);
            *(float4*)&GA[row] = make_float4(g4[0][pt], g4[1][pt], g4[2][pt], g4[3][pt]);
            *(float4*)&RA[row] = make_float4(r4[0][pt], r4[1][pt], r4[2][pt], r4[3][pt]);
            *(float4*)&SR[row] = make_float4(s_cur[0][pt] * r4[0][pt], s_cur[1][pt] * r4[1][pt],
                                             s_cur[2][pt] * r4[2][pt], s_cur[3][pt] * r4[3][pt]);
        }
        __syncthreads();

        u64t ah[4] = {xhr[0], xhr[1], xhr[2], xhr[3]};
        #pragma unroll 8
        for (int k = 0; k < UNITS; k++) {
            ulonglong2 wh2 = *(const ulonglong2*)&wh[k * UNITS + j4];
            float v0 = SR[p0 * UNITS + k];
            float v1 = SR[(p0 + 1) * UNITS + k];
            u64t s0p = pack2(v0, v0), s1p = pack2(v1, v1);
            ah[0] = ffma2(wh2.x, s0p, ah[0]); ah[1] = ffma2(wh2.x, s1p, ah[1]);
            ah[2] = ffma2(wh2.y, s0p, ah[2]); ah[3] = ffma2(wh2.y, s1p, ah[3]);
        }
        float h4[4][2];
        #pragma unroll
        for (int q = 0; q < 4; q++) {
            int u0 = (q >> 1) * 2, pt = q & 1;
            float2 t = unpack2(ah[q]);
            h4[u0][pt] = ftanh(t.x); h4[u0 + 1][pt] = ftanh(t.y);
        }
        #pragma unroll
        for (int pt = 0; pt < 2; pt++) {
            int row = (p0 + pt) * UNITS + j4;
            *(float4*)&HA[row] = make_float4(h4[0][pt], h4[1][pt], h4[2][pt], h4[3][pt]);
        }
        #pragma unroll
        for (int u = 0; u < 4; u++)
            #pragma unroll
            for (int pt = 0; pt < 2; pt++)
                s_cur[u][pt] = (1.0f - g4[u][pt]) * h4[u][pt] + z4[u][pt] * s_cur[u][pt];
        if (l < 2) {
            #pragma unroll
            for (int pt = 0; pt < 2; pt++)
                *(float4*)&sm[SM_S + (l + 1) * 2048 + (p0 + pt) * UNITS + j4] =
                    make_float4(s_cur[0][pt], s_cur[1][pt], s_cur[2][pt], s_cur[3][pt]);
        }
        __syncthreads();
    }

    // ---- value: each warp holds all 128 units for its 2 points ----
    float4 wo4 = *(const float4*)&wout[j4];
    {
        float v0 = wo4.x * s_cur[0][0] + wo4.y * s_cur[1][0] + wo4.z * s_cur[2][0] + wo4.w * s_cur[3][0];
        float v1 = wo4.x * s_cur[0][1] + wo4.y * s_cur[1][1] + wo4.z * s_cur[2][1] + wo4.w * s_cur[3][1];
        #pragma unroll
        for (int off = 16; off; off >>= 1) {
            v0 += __shfl_xor_sync(0xffffffffu, v0, off);
            v1 += __shfl_xor_sync(0xffffffffu, v1, off);
        }
        if (lane == 0) {
            float bo = bout[0];
            g_FVAL[base + p0]     = v0 + bo;
            g_FVAL[base + p0 + 1] = v1 + bo;
        }
    }

    if (!doGrad) return;

    // ---- backward ----
    float ds[4][2], Daz[4][2], Dag[4][2], Dar[4][2], Dah[4][2];
    {
        float wv[4] = {wo4.x, wo4.y, wo4.z, wo4.w};
        #pragma unroll
        for (int u = 0; u < 4; u++)
            #pragma unroll
            for (int pt = 0; pt < 2; pt++) {
                ds[u][pt] = wv[u];
                Daz[u][pt] = 0.f; Dag[u][pt] = 0.f; Dar[u][pt] = 0.f; Dah[u][pt] = 0.f;
            }
    }

    #pragma unroll 1
    for (int l = 2; l >= 0; l--) {
        float* Sin = &sm[SM_S + l * 2048];
        float* ZA  = &sm[SM_Z + l * 2048];
        float* GA  = &sm[SM_G + l * 2048];
        float* RA  = &sm[SM_R + l * 2048];
        float* HA  = &sm[SM_H + l * 2048];

        // stage A: elementwise; overwrite Z/G/H with daz/dag/dah
        {
            #pragma unroll
            for (int pt = 0; pt < 2; pt++) {
                int row = (p0 + pt) * UNITS + j4;
                float4 zq = *(const float4*)&ZA[row];
                float4 gq = *(const float4*)&GA[row];
                float4 hq = *(const float4*)&HA[row];
                float4 sq = *(const float4*)&Sin[row];
                float zs[4] = {zq.x, zq.y, zq.z, zq.w};
                float gs[4] = {gq.x, gq.y, gq.z, gq.w};
                float hs[4] = {hq.x, hq.y, hq.z, hq.w};
                float ss[4] = {sq.x, sq.y, sq.z, sq.w};
                float dazv[4], dagv[4], dahv[4];
                #pragma unroll
                for (int u = 0; u < 4; u++) {
                    float dsp = ds[u][pt];
                    float dh = dsp * (1.0f - gs[u]);
                    float dg = -dsp * hs[u];
                    float dz = dsp * ss[u];
                    dazv[u] = dz * (1.0f - zs[u] * zs[u]);
                    dagv[u] = dg * (1.0f - gs[u] * gs[u]);
                    dahv[u] = dh * (1.0f - hs[u] * hs[u]);
                    Daz[u][pt] += dazv[u]; Dag[u][pt] += dagv[u]; Dah[u][pt] += dahv[u];
                    ds[u][pt] = dsp * zs[u];
                }
                *(float4*)&ZA[row] = make_float4(dazv[0], dazv[1], dazv[2], dazv[3]);
                *(float4*)&GA[row] = make_float4(dagv[0], dagv[1], dagv[2], dagv[3]);
                *(float4*)&HA[row] = make_float4(dahv[0], dahv[1], dahv[2], dahv[3]);
            }
        }
        __syncthreads();

        // stage B: dsr = dah @ Wh^T
        float dsr[4][2];
        {
            const float* WhT = g_WT + 3 * UNITS * UNITS;
            u64t db[4];
            db[0] = db[1] = db[2] = db[3] = pack2(0.f, 0.f);
            #pragma unroll 8
            for (int k = 0; k < UNITS; k++) {
                ulonglong2 wt2 = *(const ulonglong2*)&WhT[k * UNITS + j4];
                float v0 = HA[p0 * UNITS + k];
                float v1 = HA[(p0 + 1) * UNITS + k];
                u64t s0p = pack2(v0, v0), s1p = pack2(v1, v1);
                db[0] = ffma2(wt2.x, s0p, db[0]); db[1] = ffma2(wt2.x, s1p, db[1]);
                db[2] = ffma2(wt2.y, s0p, db[2]); db[3] = ffma2(wt2.y, s1p, db[3]);
            }
            #pragma unroll
            for (int q = 0; q < 4; q++) {
                float2 t = unpack2(db[q]);
                int u0 = (q >> 1) * 2, pt = q & 1;
                dsr[u0][pt] = t.x; dsr[u0 + 1][pt] = t.y;
            }
        }

        // stage C: dar; overwrite R
        {
            #pragma unroll
            for (int pt = 0; pt < 2; pt++) {
                int row = (p0 + pt) * UNITS + j4;
                float4 rq = *(const float4*)&RA[row];
                float4 sq = *(const float4*)&Sin[row];
                float rs[4] = {rq.x, rq.y, rq.z, rq.w};
                float ss[4] = {sq.x, sq.y, sq.z, sq.w};
                float darv[4];
                #pragma unroll
                for (int u = 0; u < 4; u++) {
                    ds[u][pt] += dsr[u][pt] * rs[u];
                    darv[u] = (dsr[u][pt] * ss[u]) * (1.0f - rs[u] * rs[u]);
                    Dar[u][pt] += darv[u];
                }
                *(float4*)&RA[row] = make_float4(darv[0], darv[1], darv[2], darv[3]);
            }
        }
        __syncthreads();

        // stage D: ds += daz@Wz^T + dag@Wg^T + dar@Wr^T
        {
            const float* WzT = g_WT + 0 * UNITS * UNITS;
            const float* WgT = g_WT + 1 * UNITS * UNITS;
            const float* WrT = g_WT + 2 * UNITS * UNITS;
            u64t dd[4];
            dd[0] = pack2(ds[0][0], ds[1][0]); dd[1] = pack2(ds[0][1], ds[1][1]);
            dd[2] = pack2(ds[2][0], ds[3][0]); dd[3] = pack2(ds[2][1], ds[3][1]);
            #pragma unroll 4
            for (int k = 0; k < UNITS; k++) {
                ulonglong2 wzt = *(const ulonglong2*)&WzT[k * UNITS + j4];
                ulonglong2 wgt = *(const ulonglong2*)&WgT[k * UNITS + j4];
                ulonglong2 wrt = *(const ulonglong2*)&WrT[k * UNITS + j4];
                float z0 = ZA[p0 * UNITS + k], z1 = ZA[(p0 + 1) * UNITS + k];
                float g0 = GA[p0 * UNITS + k], g1 = GA[(p0 + 1) * UNITS + k];
                float r0 = RA[p0 * UNITS + k], r1 = RA[(p0 + 1) * UNITS + k];
                u64t z0p = pack2(z0, z0), z1p = pack2(z1, z1);
                u64t g0p = pack2(g0, g0), g1p = pack2(g1, g1);
                u64t r0p = pack2(r0, r0), r1p = pack2(r1, r1);
                dd[0] = ffma2(wzt.x, z0p, dd[0]); dd[1] = ffma2(wzt.x, z1p, dd[1]);
                dd[2] = ffma2(wzt.y, z0p, dd[2]); dd[3] = ffma2(wzt.y, z1p, dd[3]);
                dd[0] = ffma2(wgt.x, g0p, dd[0]); dd[1] = ffma2(wgt.x, g1p, dd[1]);
                dd[2] = ffma2(wgt.y, g0p, dd[2]); dd[3] = ffma2(wgt.y, g1p, dd[3]);
                dd[0] = ffma2(wrt.x, r0p, dd[0]); dd[1] = ffma2(wrt.x, r1p, dd[1]);
                dd[2] = ffma2(wrt.y, r0p, dd[2]); dd[3] = ffma2(wrt.y, r1p, dd[3]);
            }
            #pragma unroll
            for (int q = 0; q < 4; q++) {
                float2 t = unpack2(dd[q]);
                int u0 = (q >> 1) * 2, pt = q & 1;
                ds[u0][pt] = t.x; ds[u0 + 1][pt] = t.y;
            }
        }
        // next stage A writes only layer l-1 arrays at own rows: no barrier needed
    }

    // stage D(0) readers must finish before we overwrite layer-0 slots
    __syncthreads();
    {
        #pragma unroll
        for (int pt = 0; pt < 2; pt++) {
            int row = (p0 + pt) * UNITS + j4;
            float4 sq = *(const float4*)&sm[SM_S + row];
            float s0s[4] = {sq.x, sq.y, sq.z, sq.w};
            float da1[4];
            #pragma unroll
            for (int u = 0; u < 4; u++) da1[u] = ds[u][pt] * (1.0f - s0s[u] * s0s[u]);
            *(float4*)&sm[SM_Z + row] = make_float4(Daz[0][pt], Daz[1][pt], Daz[2][pt], Daz[3][pt]);
            *(float4*)&sm[SM_G + row] = make_float4(Dag[0][pt], Dag[1][pt], Dag[2][pt], Dag[3][pt]);
            *(float4*)&sm[SM_R + row] = make_float4(Dar[0][pt], Dar[1][pt], Dar[2][pt], Dar[3][pt]);
            *(float4*)&sm[SM_H + row] = make_float4(Dah[0][pt], Dah[1][pt], Dah[2][pt], Dah[3][pt]);
            *(float4*)&sm[SM_S + row] = make_float4(da1[0], da1[1], da1[2], da1[3]);
        }
    }
    __syncthreads();

    // dx = Σ_v Da_v @ U_v^T : thread = (point, 4-d group)
    if (tid < 96) {
        int p  = tid / 6;
        int dq = tid % 6;
        int d0 = dq * 4;
        float acc[4] = {0.f, 0.f, 0.f, 0.f};
        #pragma unroll 1
        for (int v = 0; v < 5; v++) {
            const float* slot =
                (v == 0) ? &sm[SM_Z] : (v == 1) ? &sm[SM_G] :
                (v == 2) ? &sm[SM_R] : (v == 3) ? &sm[SM_H] : &sm[SM_S];
            const float* Ut = g_UcatT + v * UNITS * 24;
            #pragma unroll 8
            for (int k = 0; k < UNITS; k++) {
                float a = slot[p * UNITS + k];
                float4 u = *(const float4*)&Ut[k * 24 + d0];
                acc[0] += a * u.x; acc[1] += a * u.y; acc[2] += a * u.z; acc[3] += a * u.w;
            }
        }
        #pragma unroll
        for (int i = 0; i < 4; i++) {
            int d = d0 + i;
            if (d < DD) g_FP[(base + p) * DD + d] = acc[i];
        }
    }
}

__global__ void epilogue_kernel(float* __restrict__ out)
{
    int warpId = threadIdx.x >> 5;
    int lane   = threadIdx.x & 31;
    int n = blockIdx.x * 8 + warpId;
    if (n >= NPT) return;

    const float* fp1 = &g_FP[n * DD];
    const float* x1r = &g_X[n * DD];
    int rp = (4096 + lane * NPT + n) * DD;
    const float* fpp = &g_FP[rp];
    const float* xp  = &g_X[rp];

    float part = 0.f;
    #pragma unroll
    for (int k = 0; k < DIMX; k++) {
        float viol = xp[k] - x1r[k];
        part += (fpp[k] - fp1[k]) * viol;
    }
    #pragma unroll
    for (int off = 16; off; off >>= 1) part += __shfl_xor_sync(0xffffffffu, part, off);

    if (lane == 0) {
        float term12 = part / (DELTAc * (float)MCc);
        float term11 = fp1[DIMX];
        #pragma unroll
        for (int k = 0; k < DIMX; k++) term11 += MUc * x1r[k] * fp1[k];
        out[n] = term11 + 0.5f * term12 - Rc * g_FVAL[n];

        const float* x2r = &g_X[(NPT + n) * DD];
        float prod = 1.f;
        #pragma unroll
        for (int k = 0; k < DIMX; k++) prod *= x2r[k];
        float payoff = powf(prod, 1.0f / (float)DIMX);
        payoff = fmaxf(payoff, 0.f);
        out[NPT + n] = g_FVAL[NPT + n] - payoff;
    }
}

extern "C" void kernel_launch(void* const* d_in, const int* in_sizes, int n_in,
                              void* d_out, int out_size)
{
    (void)in_sizes; (void)n_in; (void)out_size;
    const float* inputs = (const float*)d_in[0];
    const float* eps    = (const float*)d_in[1];
    const float* w1  = (const float*)d_in[2];
    const float* b1  = (const float*)d_in[3];
    const float* uzl = (const float*)d_in[4];
    const float* wzl = (const float*)d_in[5];
    const float* bzl = (const float*)d_in[6];
    const float* ugl = (const float*)d_in[7];
    const float* wgl = (const float*)d_in[8];
    const float* bgl = (const float*)d_in[9];
    const float* url = (const float*)d_in[10];
    const float* wrl = (const float*)d_in[11];
    const float* brl = (const float*)d_in[12];
    const float* uhl = (const float*)d_in[13];
    const float* whl = (const float*)d_in[14];
    const float* bhl = (const float*)d_in[15];
    const float* w   = (const float*)d_in[16];
    const float* b   = (const float*)d_in[17];
    float* out = (float*)d_out;

    const int smem_bytes = SM_TOT * (int)sizeof(float);
    static bool attr_set = false;
    if (!attr_set) {
        cudaFuncSetAttribute(dgm_main, cudaFuncAttributeMaxDynamicSharedMemorySize, smem_bytes);
        attr_set = true;
    }

    prep_kernel<<<64, 256>>>(wzl, wgl, wrl, whl, uzl, ugl, url, uhl, w1);
    build_kernel<<<BTOT / 256, 256>>>(inputs, eps);
    dgm_main<<<NTILES, THREADS, smem_bytes>>>(w1, b1, uzl, wzl, bzl, ugl, wgl, bgl,
                                              url, wrl, brl, uhl, whl, bhl, w, b);
    epilogue_kernel<<<NPT / 8, 256>>>(out);
}